// round 7
// baseline (speedup 1.0000x reference)
#include <cuda_runtime.h>
#include <cuda_fp16.h>
#include <cstdint>

// ---------------------------------------------------------------------------
// Problem dims
// ---------------------------------------------------------------------------
#define HID   2048
#define CH    4096
#define SEQ   4096
#define BATCH 4
#define MROWS (BATCH * SEQ)   // 16384

// ---------------------------------------------------------------------------
// Device scratch (allocation-free rule)
// ---------------------------------------------------------------------------
__device__ __half g_hs16  [(size_t)MROWS * HID];   // hs as fp16
__device__ __half g_win16 [(size_t)CH * HID];      // w_in as fp16
__device__ __half g_wout16[(size_t)HID * CH];      // w_out as fp16
__device__ float  g_x     [(size_t)MROWS * CH];    // after in-proj (fp32)
__device__ __half g_y     [(size_t)MROWS * CH];    // conv+silu (fp16)

// ---------------------------------------------------------------------------
// PTX helpers (arch-generic: cp.async / ldmatrix / mma.sync)
// ---------------------------------------------------------------------------
__device__ __forceinline__ uint32_t smem_u32(const void* p) {
    uint32_t a;
    asm("{ .reg .u64 t; cvta.to.shared.u64 t, %1; cvt.u32.u64 %0, t; }" : "=r"(a) : "l"(p));
    return a;
}
__device__ __forceinline__ void cp16(uint32_t dst, const void* src) {
    asm volatile("cp.async.cg.shared.global [%0], [%1], 16;" :: "r"(dst), "l"(src));
}
__device__ __forceinline__ void cp_commit() { asm volatile("cp.async.commit_group;" ::: "memory"); }
__device__ __forceinline__ void cp_wait1()  { asm volatile("cp.async.wait_group 1;"  ::: "memory"); }
__device__ __forceinline__ void cp_wait0()  { asm volatile("cp.async.wait_group 0;"  ::: "memory"); }

__device__ __forceinline__ void ldsm_x4(uint32_t* r, uint32_t addr) {
    asm volatile("ldmatrix.sync.aligned.m8n8.x4.shared.b16 {%0,%1,%2,%3}, [%4];"
        : "=r"(r[0]), "=r"(r[1]), "=r"(r[2]), "=r"(r[3]) : "r"(addr));
}
__device__ __forceinline__ void mma16816(float* c, const uint32_t* a, const uint32_t* b) {
    asm volatile(
        "mma.sync.aligned.m16n8k16.row.col.f32.f16.f16.f32 "
        "{%0,%1,%2,%3}, {%4,%5,%6,%7}, {%8,%9}, {%0,%1,%2,%3};"
        : "+f"(c[0]), "+f"(c[1]), "+f"(c[2]), "+f"(c[3])
        : "r"(a[0]), "r"(a[1]), "r"(a[2]), "r"(a[3]), "r"(b[0]), "r"(b[1]));
}

// ---------------------------------------------------------------------------
// GEMM: C[m,n] = sum_k A[m,k]*B[n,k] + bias[n]   (fp16 in, fp32 acc)
// CTA tile 256x128, 512 threads / 16 warps (8x2 grid, warp tile 32x64),
// BK=64, 3-stage cp.async.  LDA=72 (144B rows) -> conflict-free ldsm.
// smem/stage: (256+128) x 72 x 2B = 55296 B; 3 stages = 165888 B, occ 1
// (16 warps; RF-bound anyway: ~115 regs x 512 thr).
// L2 fill traffic: M*N*K*2*(1/256+1/128) = 3.2 GB/GEMM (was 4.3).
// ---------------------------------------------------------------------------
#define BM    256
#define BN    128
#define BK    64
#define LDA   72
#define MATA  (BM * LDA)                  // 18432 elems
#define MATB  (BN * LDA)                  // 9216 elems
#define STAGE_ELEMS (MATA + MATB)         // 27648
#define STAGES 3
#define GEMM_SMEM (STAGES * STAGE_ELEMS * 2)  // 165888 bytes

__global__ void __launch_bounds__(512, 1)
gemm_fp16(const __half* __restrict__ A, const __half* __restrict__ B,
          const float* __restrict__ bias, float* __restrict__ C,
          int M, int N, int K)
{
    extern __shared__ __align__(16) char smraw[];
    const uint32_t sbase = smem_u32(smraw);

    const int tid  = threadIdx.x;
    const int wid  = tid >> 5;
    const int lane = tid & 31;
    const int bm   = blockIdx.y * BM;
    const int bn   = blockIdx.x * BN;
    const int wm   = (wid & 7) * 32;     // 8 warp rows
    const int wn   = (wid >> 3) * 64;    // 2 warp cols

    float acc[2][8][4];
#pragma unroll
    for (int i = 0; i < 2; i++)
#pragma unroll
        for (int j = 0; j < 8; j++)
#pragma unroll
            for (int k = 0; k < 4; k++) acc[i][j][k] = 0.0f;

    const int nchunks = K / BK;

    // stage loader: A 256x64 (2048 cp16), B 128x64 (1024 cp16) over 512 thr
    auto load_stage = [&](int slot, int k0) {
        const uint32_t st = sbase + (uint32_t)slot * STAGE_ELEMS * 2;
#pragma unroll
        for (int i = 0; i < 4; i++) {
            const int c   = tid + 512 * i;       // 0..2047
            const int row = c >> 3;
            const int kc  = (c & 7) * 8;
            cp16(st + (uint32_t)(row * LDA + kc) * 2,
                 A + (size_t)(bm + row) * K + k0 + kc);
        }
#pragma unroll
        for (int i = 0; i < 2; i++) {
            const int c   = tid + 512 * i;       // 0..1023
            const int row = c >> 3;
            const int kc  = (c & 7) * 8;
            cp16(st + MATA * 2 + (uint32_t)(row * LDA + kc) * 2,
                 B + (size_t)(bn + row) * K + k0 + kc);
        }
        cp_commit();
    };

    // prologue: 2 stages in flight
    load_stage(0, 0);
    load_stage(1, BK);

    for (int i = 0; i < nchunks; i++) {
        if (i + 1 < nchunks) cp_wait1(); else cp_wait0();
        __syncthreads();

        if (i + 2 < nchunks) load_stage((i + 2) % STAGES, (i + 2) * BK);

        const uint32_t st = sbase + (uint32_t)(i % STAGES) * STAGE_ELEMS * 2;
        const uint32_t sA = st;
        const uint32_t sB = st + MATA * 2;

#pragma unroll
        for (int kk = 0; kk < 4; kk++) {           // four k16 sub-steps
            uint32_t a[2][4];
#pragma unroll
            for (int mt = 0; mt < 2; mt++) {
                const int row = wm + mt * 16 + (lane & 15);
                const int col = kk * 16 + (lane >> 4) * 8;
                ldsm_x4(a[mt], sA + (uint32_t)(row * LDA + col) * 2);
            }
            uint32_t b[4][4];
#pragma unroll
            for (int q = 0; q < 4; q++) {
                const int nrow = wn + q * 16 + (lane & 7) + ((lane >> 4) << 3);
                const int col  = kk * 16 + ((lane >> 3) & 1) * 8;
                ldsm_x4(b[q], sB + (uint32_t)(nrow * LDA + col) * 2);
            }
#pragma unroll
            for (int mt = 0; mt < 2; mt++)
#pragma unroll
                for (int q = 0; q < 4; q++)
#pragma unroll
                    for (int h = 0; h < 2; h++)
                        mma16816(acc[mt][q * 2 + h], a[mt], &b[q][h * 2]);
        }
        // single barrier per iteration: slot (i+2)%3 was last read in iter
        // i-1, ordered by this iteration's __syncthreads.
    }

    // --- epilogue: fused bias ---
    const int r  = lane >> 2;
    const int cc = (lane & 3) * 2;
#pragma unroll
    for (int mt = 0; mt < 2; mt++) {
        const int row0 = bm + wm + mt * 16;
#pragma unroll
        for (int nt = 0; nt < 8; nt++) {
            const int col0 = bn + wn + nt * 8;
            const float2 bv = *reinterpret_cast<const float2*>(bias + col0 + cc);
            float* p0 = C + (size_t)(row0 + r) * N + col0 + cc;
            float* p1 = C + (size_t)(row0 + r + 8) * N + col0 + cc;
            float2 o0, o1;
            o0.x = acc[mt][nt][0] + bv.x;  o0.y = acc[mt][nt][1] + bv.y;
            o1.x = acc[mt][nt][2] + bv.x;  o1.y = acc[mt][nt][3] + bv.y;
            *reinterpret_cast<float2*>(p0) = o0;
            *reinterpret_cast<float2*>(p1) = o1;
        }
    }
}

// ---------------------------------------------------------------------------
// fp32 -> fp16 convert
// ---------------------------------------------------------------------------
__global__ void __launch_bounds__(256)
convert_fp16(const float* __restrict__ src, __half* __restrict__ dst, long long n4)
{
    const long long i = (long long)blockIdx.x * blockDim.x + threadIdx.x;
    if (i >= n4) return;
    const float4 v = reinterpret_cast<const float4*>(src)[i];
    __half2 p0, p1;
    p0.x = __float2half(v.x); p0.y = __float2half(v.y);
    p1.x = __float2half(v.z); p1.y = __float2half(v.w);
    reinterpret_cast<__half2*>(dst)[2 * i]     = p0;
    reinterpret_cast<__half2*>(dst)[2 * i + 1] = p1;
}

// ---------------------------------------------------------------------------
// Causal depthwise conv (K=4) + bias + SiLU -> fp16
// ---------------------------------------------------------------------------
#define SCH 256
__global__ void __launch_bounds__(256)
conv_silu(const float* __restrict__ x, const float* __restrict__ cw,
          const float* __restrict__ cb, __half* __restrict__ y)
{
    const int c  = blockIdx.x * 256 + threadIdx.x;   // channel
    const int b  = blockIdx.z;
    const int s0 = blockIdx.y * SCH;

    const float4 w4 = *reinterpret_cast<const float4*>(cw + (size_t)c * 4);
    const float bias = cb[c];
    const size_t base = ((size_t)b * SEQ) * CH + c;

    float xm3, xm2, xm1;
    if (s0 == 0) { xm3 = xm2 = xm1 = 0.0f; }
    else {
        xm3 = x[base + (size_t)(s0 - 3) * CH];
        xm2 = x[base + (size_t)(s0 - 2) * CH];
        xm1 = x[base + (size_t)(s0 - 1) * CH];
    }

    for (int s = s0; s < s0 + SCH; s++) {
        const float xc = x[base + (size_t)s * CH];
        float acc = bias;
        acc = fmaf(w4.x, xm3, acc);
        acc = fmaf(w4.y, xm2, acc);
        acc = fmaf(w4.z, xm1, acc);
        acc = fmaf(w4.w, xc,  acc);
        const float v = acc / (1.0f + __expf(-acc));
        y[base + (size_t)s * CH] = __float2half(v);
        xm3 = xm2; xm2 = xm1; xm1 = xc;
    }
}

// ---------------------------------------------------------------------------
// Launch: hidden_states, w_in, b_in, conv_w, conv_b, w_out, b_out
// ---------------------------------------------------------------------------
extern "C" void kernel_launch(void* const* d_in, const int* in_sizes, int n_in,
                              void* d_out, int out_size)
{
    const float* hs     = (const float*)d_in[0];
    const float* w_in   = (const float*)d_in[1];
    const float* b_in   = (const float*)d_in[2];
    const float* conv_w = (const float*)d_in[3];
    const float* conv_b = (const float*)d_in[4];
    const float* w_out  = (const float*)d_in[5];
    const float* b_out  = (const float*)d_in[6];
    float* out = (float*)d_out;

    __half *hs16, *win16, *wout16, *ybuf;
    float *xbuf;
    cudaGetSymbolAddress((void**)&hs16,   g_hs16);
    cudaGetSymbolAddress((void**)&win16,  g_win16);
    cudaGetSymbolAddress((void**)&wout16, g_wout16);
    cudaGetSymbolAddress((void**)&xbuf,   g_x);
    cudaGetSymbolAddress((void**)&ybuf,   g_y);

    cudaFuncSetAttribute(gemm_fp16, cudaFuncAttributeMaxDynamicSharedMemorySize, GEMM_SMEM);

    // fp16 conversions
    {
        long long n4 = (long long)MROWS * HID / 4;
        convert_fp16<<<(unsigned)(n4 / 256), 256>>>(hs, hs16, n4);
        n4 = (long long)CH * HID / 4;
        convert_fp16<<<(unsigned)(n4 / 256), 256>>>(w_in, win16, n4);
        n4 = (long long)HID * CH / 4;
        convert_fp16<<<(unsigned)(n4 / 256), 256>>>(w_out, wout16, n4);
    }

    // GEMM1: x = hs @ w_in^T + b_in   [16384, 4096]
    {
        dim3 grid(CH / BN, MROWS / BM);   // (32, 64)
        gemm_fp16<<<grid, 512, GEMM_SMEM>>>(hs16, win16, b_in, xbuf, MROWS, CH, HID);
    }

    // conv + SiLU -> y (fp16)
    {
        dim3 grid(CH / 256, SEQ / SCH, BATCH);  // (16, 16, 4)
        conv_silu<<<grid, 256>>>(xbuf, conv_w, conv_b, ybuf);
    }

    // GEMM2: out = y @ w_out^T + b_out  [16384, 2048]
    {
        dim3 grid(HID / BN, MROWS / BM);  // (16, 64)
        gemm_fp16<<<grid, 512, GEMM_SMEM>>>(ybuf, wout16, b_out, out, MROWS, HID, CH);
    }
}

// round 8
// speedup vs baseline: 1.1747x; 1.1747x over previous
#include <cuda_runtime.h>
#include <cuda_fp16.h>
#include <cstdint>

// ---------------------------------------------------------------------------
// Problem dims
// ---------------------------------------------------------------------------
#define HID   2048
#define CH    4096
#define SEQ   4096
#define BATCH 4
#define MROWS (BATCH * SEQ)   // 16384

// ---------------------------------------------------------------------------
// Device scratch (allocation-free rule)
// ---------------------------------------------------------------------------
__device__ __half g_hs16  [(size_t)MROWS * HID];   // hs as fp16
__device__ __half g_win16 [(size_t)CH * HID];      // w_in as fp16
__device__ __half g_wout16[(size_t)HID * CH];      // w_out as fp16
__device__ __half g_x     [(size_t)MROWS * CH];    // after in-proj (fp16)
__device__ __half g_y     [(size_t)MROWS * CH];    // conv+silu (fp16)

// ---------------------------------------------------------------------------
// PTX helpers (arch-generic: cp.async / ldmatrix / mma.sync)
// ---------------------------------------------------------------------------
__device__ __forceinline__ uint32_t smem_u32(const void* p) {
    uint32_t a;
    asm("{ .reg .u64 t; cvta.to.shared.u64 t, %1; cvt.u32.u64 %0, t; }" : "=r"(a) : "l"(p));
    return a;
}
__device__ __forceinline__ void cp16(uint32_t dst, const void* src) {
    asm volatile("cp.async.cg.shared.global [%0], [%1], 16;" :: "r"(dst), "l"(src));
}
__device__ __forceinline__ void cp_commit() { asm volatile("cp.async.commit_group;" ::: "memory"); }
__device__ __forceinline__ void cp_wait1()  { asm volatile("cp.async.wait_group 1;"  ::: "memory"); }
__device__ __forceinline__ void cp_wait0()  { asm volatile("cp.async.wait_group 0;"  ::: "memory"); }

__device__ __forceinline__ void ldsm_x4(uint32_t* r, uint32_t addr) {
    asm volatile("ldmatrix.sync.aligned.m8n8.x4.shared.b16 {%0,%1,%2,%3}, [%4];"
        : "=r"(r[0]), "=r"(r[1]), "=r"(r[2]), "=r"(r[3]) : "r"(addr));
}
__device__ __forceinline__ void mma16816(float* c, const uint32_t* a, const uint32_t* b) {
    asm volatile(
        "mma.sync.aligned.m16n8k16.row.col.f32.f16.f16.f32 "
        "{%0,%1,%2,%3}, {%4,%5,%6,%7}, {%8,%9}, {%0,%1,%2,%3};"
        : "+f"(c[0]), "+f"(c[1]), "+f"(c[2]), "+f"(c[3])
        : "r"(a[0]), "r"(a[1]), "r"(a[2]), "r"(a[3]), "r"(b[0]), "r"(b[1]));
}

// ---------------------------------------------------------------------------
// GEMM: C[m,n] = sum_k A[m,k]*B[n,k] + bias[n]   (fp16 in, fp32 acc)
// R6 config: CTA 128x128, 8 warps (warp tile 32x64), BK=64, 3 stages, occ 2.
// LDA=72 (144B rows) -> conflict-free ldsm.  Output type templated.
// ---------------------------------------------------------------------------
#define BK    64
#define LDA   72
#define MATB  (128 * LDA)                 // 9216 elems / tile
#define STAGE_ELEMS (2 * MATB)            // A, B
#define STAGES 3
#define GEMM_SMEM (STAGES * STAGE_ELEMS * 2)  // 110592 bytes

template <typename OutT>
__global__ void __launch_bounds__(256, 2)
gemm_fp16(const __half* __restrict__ A, const __half* __restrict__ B,
          const float* __restrict__ bias, OutT* __restrict__ C,
          int M, int N, int K)
{
    extern __shared__ __align__(16) char smraw[];
    const uint32_t sbase = smem_u32(smraw);

    const int tid  = threadIdx.x;
    const int wid  = tid >> 5;
    const int lane = tid & 31;
    const int bm   = blockIdx.y * 128;
    const int bn   = blockIdx.x * 128;
    const int wm   = (wid & 3) * 32;     // warp row offset
    const int wn   = (wid >> 2) * 64;    // warp col offset

    float acc[2][8][4];
#pragma unroll
    for (int i = 0; i < 2; i++)
#pragma unroll
        for (int j = 0; j < 8; j++)
#pragma unroll
            for (int k = 0; k < 4; k++) acc[i][j][k] = 0.0f;

    const int nchunks = K / BK;

    // stage loader: 128 rows x 64 cols fp16 per matrix = 1024 cp16 / 256 thr
    auto load_stage = [&](int slot, int k0) {
        const uint32_t st = sbase + (uint32_t)slot * STAGE_ELEMS * 2;
#pragma unroll
        for (int i = 0; i < 4; i++) {
            const int c   = tid + 256 * i;       // 0..1023
            const int row = c >> 3;
            const int kc  = (c & 7) * 8;
            const uint32_t soff = (uint32_t)(row * LDA + kc) * 2;
            cp16(st + soff,            A + (size_t)(bm + row) * K + k0 + kc);
            cp16(st + MATB * 2 + soff, B + (size_t)(bn + row) * K + k0 + kc);
        }
        cp_commit();
    };

    // one k16 sub-step of the 128x128 warp-tiled MMA
    auto do_kk = [&](uint32_t sA, uint32_t sB, int kk) {
        uint32_t a[2][4];
#pragma unroll
        for (int mt = 0; mt < 2; mt++) {
            const int row = wm + mt * 16 + (lane & 15);
            const int col = kk * 16 + (lane >> 4) * 8;
            ldsm_x4(a[mt], sA + (uint32_t)(row * LDA + col) * 2);
        }
        uint32_t b[4][4];
#pragma unroll
        for (int q = 0; q < 4; q++) {
            const int nrow = wn + q * 16 + (lane & 7) + ((lane >> 4) << 3);
            const int col  = kk * 16 + ((lane >> 3) & 1) * 8;
            ldsm_x4(b[q], sB + (uint32_t)(nrow * LDA + col) * 2);
        }
#pragma unroll
        for (int mt = 0; mt < 2; mt++)
#pragma unroll
            for (int q = 0; q < 4; q++)
#pragma unroll
                for (int h = 0; h < 2; h++)
                    mma16816(acc[mt][q * 2 + h], a[mt], &b[q][h * 2]);
    };

    // prologue: 2 stages in flight
    load_stage(0, 0);
    load_stage(1, BK);

    for (int i = 0; i < nchunks; i++) {
        if (i + 1 < nchunks) cp_wait1(); else cp_wait0();
        __syncthreads();

        const uint32_t st = sbase + (uint32_t)(i % STAGES) * STAGE_ELEMS * 2;
        const uint32_t sA = st;
        const uint32_t sB = st + MATB * 2;

        // kk=0 first so the cp.async burst overlaps tensor work
        do_kk(sA, sB, 0);
        if (i + 2 < nchunks) load_stage((i + 2) % STAGES, (i + 2) * BK);
        do_kk(sA, sB, 1);
        do_kk(sA, sB, 2);
        do_kk(sA, sB, 3);
        // single barrier per iteration: slot (i+2)%3 was last read in iter
        // i-1, ordered by this iteration's __syncthreads.
    }

    // --- epilogue: fused bias, OutT = float (fp32) or __half ---
    const int r  = lane >> 2;
    const int cc = (lane & 3) * 2;
#pragma unroll
    for (int mt = 0; mt < 2; mt++) {
        const int row0 = bm + wm + mt * 16;
#pragma unroll
        for (int nt = 0; nt < 8; nt++) {
            const int col0 = bn + wn + nt * 8;
            const float2 bv = *reinterpret_cast<const float2*>(bias + col0 + cc);
            const float v00 = acc[mt][nt][0] + bv.x, v01 = acc[mt][nt][1] + bv.y;
            const float v10 = acc[mt][nt][2] + bv.x, v11 = acc[mt][nt][3] + bv.y;
            OutT* p0 = C + (size_t)(row0 + r) * N + col0 + cc;
            OutT* p1 = C + (size_t)(row0 + r + 8) * N + col0 + cc;
            if constexpr (sizeof(OutT) == 4) {
                float2 o0, o1;
                o0.x = v00; o0.y = v01; o1.x = v10; o1.y = v11;
                *reinterpret_cast<float2*>(p0) = o0;
                *reinterpret_cast<float2*>(p1) = o1;
            } else {
                __half2 o0, o1;
                o0.x = __float2half(v00); o0.y = __float2half(v01);
                o1.x = __float2half(v10); o1.y = __float2half(v11);
                *reinterpret_cast<__half2*>(p0) = o0;
                *reinterpret_cast<__half2*>(p1) = o1;
            }
        }
    }
}

// ---------------------------------------------------------------------------
// fp32 -> fp16 convert
// ---------------------------------------------------------------------------
__global__ void __launch_bounds__(256)
convert_fp16(const float* __restrict__ src, __half* __restrict__ dst, long long n4)
{
    const long long i = (long long)blockIdx.x * blockDim.x + threadIdx.x;
    if (i >= n4) return;
    const float4 v = reinterpret_cast<const float4*>(src)[i];
    __half2 p0, p1;
    p0.x = __float2half(v.x); p0.y = __float2half(v.y);
    p1.x = __float2half(v.z); p1.y = __float2half(v.w);
    reinterpret_cast<__half2*>(dst)[2 * i]     = p0;
    reinterpret_cast<__half2*>(dst)[2 * i + 1] = p1;
}

// ---------------------------------------------------------------------------
// Causal depthwise conv (K=4) + bias + SiLU, fp16 in -> fp16 out
// ---------------------------------------------------------------------------
#define SCH 256
__global__ void __launch_bounds__(256)
conv_silu(const __half* __restrict__ x, const float* __restrict__ cw,
          const float* __restrict__ cb, __half* __restrict__ y)
{
    const int c  = blockIdx.x * 256 + threadIdx.x;   // channel
    const int b  = blockIdx.z;
    const int s0 = blockIdx.y * SCH;

    const float4 w4 = *reinterpret_cast<const float4*>(cw + (size_t)c * 4);
    const float bias = cb[c];
    const size_t base = ((size_t)b * SEQ) * CH + c;

    float xm3, xm2, xm1;
    if (s0 == 0) { xm3 = xm2 = xm1 = 0.0f; }
    else {
        xm3 = __half2float(x[base + (size_t)(s0 - 3) * CH]);
        xm2 = __half2float(x[base + (size_t)(s0 - 2) * CH]);
        xm1 = __half2float(x[base + (size_t)(s0 - 1) * CH]);
    }

    for (int s = s0; s < s0 + SCH; s++) {
        const float xc = __half2float(x[base + (size_t)s * CH]);
        float acc = bias;
        acc = fmaf(w4.x, xm3, acc);
        acc = fmaf(w4.y, xm2, acc);
        acc = fmaf(w4.z, xm1, acc);
        acc = fmaf(w4.w, xc,  acc);
        const float v = acc / (1.0f + __expf(-acc));
        y[base + (size_t)s * CH] = __float2half(v);
        xm3 = xm2; xm2 = xm1; xm1 = xc;
    }
}

// ---------------------------------------------------------------------------
// Launch: hidden_states, w_in, b_in, conv_w, conv_b, w_out, b_out
// ---------------------------------------------------------------------------
extern "C" void kernel_launch(void* const* d_in, const int* in_sizes, int n_in,
                              void* d_out, int out_size)
{
    const float* hs     = (const float*)d_in[0];
    const float* w_in   = (const float*)d_in[1];
    const float* b_in   = (const float*)d_in[2];
    const float* conv_w = (const float*)d_in[3];
    const float* conv_b = (const float*)d_in[4];
    const float* w_out  = (const float*)d_in[5];
    const float* b_out  = (const float*)d_in[6];
    float* out = (float*)d_out;

    __half *hs16, *win16, *wout16, *xbuf, *ybuf;
    cudaGetSymbolAddress((void**)&hs16,   g_hs16);
    cudaGetSymbolAddress((void**)&win16,  g_win16);
    cudaGetSymbolAddress((void**)&wout16, g_wout16);
    cudaGetSymbolAddress((void**)&xbuf,   g_x);
    cudaGetSymbolAddress((void**)&ybuf,   g_y);

    cudaFuncSetAttribute(gemm_fp16<__half>, cudaFuncAttributeMaxDynamicSharedMemorySize, GEMM_SMEM);
    cudaFuncSetAttribute(gemm_fp16<float>,  cudaFuncAttributeMaxDynamicSharedMemorySize, GEMM_SMEM);

    // fp16 conversions
    {
        long long n4 = (long long)MROWS * HID / 4;
        convert_fp16<<<(unsigned)(n4 / 256), 256>>>(hs, hs16, n4);
        n4 = (long long)CH * HID / 4;
        convert_fp16<<<(unsigned)(n4 / 256), 256>>>(w_in, win16, n4);
        n4 = (long long)HID * CH / 4;
        convert_fp16<<<(unsigned)(n4 / 256), 256>>>(w_out, wout16, n4);
    }

    // GEMM1: x = hs @ w_in^T + b_in   [16384, 4096]  (fp16 out)
    {
        dim3 grid(CH / 128, MROWS / 128);   // (32, 128)
        gemm_fp16<__half><<<grid, 256, GEMM_SMEM>>>(hs16, win16, b_in, xbuf,
                                                    MROWS, CH, HID);
    }

    // conv + SiLU -> y (fp16)
    {
        dim3 grid(CH / 256, SEQ / SCH, BATCH);  // (16, 16, 4)
        conv_silu<<<grid, 256>>>(xbuf, conv_w, conv_b, ybuf);
    }

    // GEMM2: out = y @ w_out^T + b_out  [16384, 2048]  (fp32 out)
    {
        dim3 grid(HID / 128, MROWS / 128);  // (16, 128)
        gemm_fp16<float><<<grid, 256, GEMM_SMEM>>>(ybuf, wout16, b_out, out,
                                                   MROWS, HID, CH);
    }
}

// round 9
// speedup vs baseline: 1.2661x; 1.0778x over previous
#include <cuda_runtime.h>
#include <cuda_fp16.h>
#include <cstdint>

// ---------------------------------------------------------------------------
// Problem dims
// ---------------------------------------------------------------------------
#define HID   2048
#define CH    4096
#define SEQ   4096
#define BATCH 4
#define MROWS (BATCH * SEQ)   // 16384

// ---------------------------------------------------------------------------
// Device scratch (allocation-free rule)
// ---------------------------------------------------------------------------
__device__ __half g_hs16  [(size_t)MROWS * HID];   // hs as fp16
__device__ __half g_win16 [(size_t)CH * HID];      // w_in as fp16
__device__ __half g_wout16[(size_t)HID * CH];      // w_out as fp16
__device__ __half g_x     [(size_t)MROWS * CH];    // after in-proj (fp16)
__device__ __half g_y     [(size_t)MROWS * CH];    // conv+silu (fp16)

// ---------------------------------------------------------------------------
// PTX helpers (arch-generic: cp.async / ldmatrix / mma.sync)
// ---------------------------------------------------------------------------
__device__ __forceinline__ uint32_t smem_u32(const void* p) {
    uint32_t a;
    asm("{ .reg .u64 t; cvta.to.shared.u64 t, %1; cvt.u32.u64 %0, t; }" : "=r"(a) : "l"(p));
    return a;
}
__device__ __forceinline__ void cp16(uint32_t dst, const void* src) {
    asm volatile("cp.async.cg.shared.global [%0], [%1], 16;" :: "r"(dst), "l"(src));
}
__device__ __forceinline__ void cp_commit() { asm volatile("cp.async.commit_group;" ::: "memory"); }
__device__ __forceinline__ void cp_wait2()  { asm volatile("cp.async.wait_group 2;"  ::: "memory"); }
__device__ __forceinline__ void cp_wait0()  { asm volatile("cp.async.wait_group 0;"  ::: "memory"); }

__device__ __forceinline__ void ldsm_x4(uint32_t* r, uint32_t addr) {
    asm volatile("ldmatrix.sync.aligned.m8n8.x4.shared.b16 {%0,%1,%2,%3}, [%4];"
        : "=r"(r[0]), "=r"(r[1]), "=r"(r[2]), "=r"(r[3]) : "r"(addr));
}
__device__ __forceinline__ void mma16816(float* c, const uint32_t* a, const uint32_t* b) {
    asm volatile(
        "mma.sync.aligned.m16n8k16.row.col.f32.f16.f16.f32 "
        "{%0,%1,%2,%3}, {%4,%5,%6,%7}, {%8,%9}, {%0,%1,%2,%3};"
        : "+f"(c[0]), "+f"(c[1]), "+f"(c[2]), "+f"(c[3])
        : "r"(a[0]), "r"(a[1]), "r"(a[2]), "r"(a[3]), "r"(b[0]), "r"(b[1]));
}

// ---------------------------------------------------------------------------
// GEMM: C[m,n] = sum_k A[m,k]*B[n,k] + bias[n]   (fp16 in, fp32 acc)
// CTA 128x128, 8 warps (warp tile 32x64), BK=64, 3 stages, occ 2.
// LDA=72 (144B rows) -> conflict-free ldsm. A/B cp16 halves issued after
// kk=0 / kk=1 respectively to spread LSU pressure across the chunk.
// ---------------------------------------------------------------------------
#define BK    64
#define LDA   72
#define MATB  (128 * LDA)                 // 9216 elems / tile
#define STAGE_ELEMS (2 * MATB)            // A, B
#define STAGES 3
#define GEMM_SMEM (STAGES * STAGE_ELEMS * 2)  // 110592 bytes

template <typename OutT>
__global__ void __launch_bounds__(256, 2)
gemm_fp16(const __half* __restrict__ A, const __half* __restrict__ B,
          const float* __restrict__ bias, OutT* __restrict__ C,
          int M, int N, int K)
{
    extern __shared__ __align__(16) char smraw[];
    const uint32_t sbase = smem_u32(smraw);

    const int tid  = threadIdx.x;
    const int wid  = tid >> 5;
    const int lane = tid & 31;
    const int bm   = blockIdx.y * 128;
    const int bn   = blockIdx.x * 128;
    const int wm   = (wid & 3) * 32;     // warp row offset
    const int wn   = (wid >> 2) * 64;    // warp col offset

    // precomputed per-warp ldsm byte offsets (vary only by +kk*32 in-loop)
    uint32_t aBase[2], bBase[4];
#pragma unroll
    for (int mt = 0; mt < 2; mt++)
        aBase[mt] = (uint32_t)((wm + mt * 16 + (lane & 15)) * LDA + (lane >> 4) * 8) * 2;
#pragma unroll
    for (int q = 0; q < 4; q++)
        bBase[q] = (uint32_t)((wn + q * 16 + (lane & 7) + ((lane >> 4) << 3)) * LDA
                              + ((lane >> 3) & 1) * 8) * 2;

    // loader offsets
    const int lrow = tid >> 3;
    const int lkc  = (tid & 7) * 8;
    const uint32_t lsoff = (uint32_t)(lrow * LDA + lkc) * 2;

    float acc[2][8][4];
#pragma unroll
    for (int i = 0; i < 2; i++)
#pragma unroll
        for (int j = 0; j < 8; j++)
#pragma unroll
            for (int k = 0; k < 4; k++) acc[i][j][k] = 0.0f;

    const int nchunks = K / BK;

    // half-stage loaders (A half / B half), each its own commit group
    auto load_A = [&](int slot, int k0) {
        const uint32_t st = sbase + (uint32_t)slot * STAGE_ELEMS * 2;
#pragma unroll
        for (int i = 0; i < 4; i++)
            cp16(st + lsoff + (uint32_t)(32 * i) * LDA * 2,
                 A + (size_t)(bm + lrow + 32 * i) * K + k0 + lkc);
        cp_commit();
    };
    auto load_B = [&](int slot, int k0) {
        const uint32_t st = sbase + (uint32_t)slot * STAGE_ELEMS * 2 + MATB * 2;
#pragma unroll
        for (int i = 0; i < 4; i++)
            cp16(st + lsoff + (uint32_t)(32 * i) * LDA * 2,
                 B + (size_t)(bn + lrow + 32 * i) * K + k0 + lkc);
        cp_commit();
    };

    auto do_kk = [&](uint32_t sA, uint32_t sB, int kk) {
        const uint32_t ko = (uint32_t)kk * 32;
        uint32_t a[2][4];
#pragma unroll
        for (int mt = 0; mt < 2; mt++) ldsm_x4(a[mt], sA + aBase[mt] + ko);
        uint32_t b[4][4];
#pragma unroll
        for (int q = 0; q < 4; q++)    ldsm_x4(b[q], sB + bBase[q] + ko);
#pragma unroll
        for (int mt = 0; mt < 2; mt++)
#pragma unroll
            for (int q = 0; q < 4; q++)
#pragma unroll
                for (int h = 0; h < 2; h++)
                    mma16816(acc[mt][q * 2 + h], a[mt], &b[q][h * 2]);
    };

    // prologue: 2 stages in flight (4 commit groups)
    load_A(0, 0);      load_B(0, 0);
    load_A(1, BK);     load_B(1, BK);

    for (int i = 0; i < nchunks; i++) {
        if (i + 1 < nchunks) cp_wait2(); else cp_wait0();
        __syncthreads();

        const uint32_t st = sbase + (uint32_t)(i % STAGES) * STAGE_ELEMS * 2;
        const uint32_t sA = st;
        const uint32_t sB = st + MATB * 2;
        const bool pf = (i + 2 < nchunks);
        const int  ps = (i + 2) % STAGES;
        const int  pk = (i + 2) * BK;

        do_kk(sA, sB, 0);
        if (pf) load_A(ps, pk);
        do_kk(sA, sB, 1);
        if (pf) load_B(ps, pk);
        do_kk(sA, sB, 2);
        do_kk(sA, sB, 3);
        // single barrier per iteration: slot (i+2)%3 was last read in iter
        // i-1, ordered by this iteration's __syncthreads.
    }

    // --- epilogue: fused bias ---
    const int r  = lane >> 2;
    const int cc = (lane & 3) * 2;
#pragma unroll
    for (int mt = 0; mt < 2; mt++) {
        const int row0 = bm + wm + mt * 16;
#pragma unroll
        for (int nt = 0; nt < 8; nt++) {
            const int col0 = bn + wn + nt * 8;
            const float2 bv = *reinterpret_cast<const float2*>(bias + col0 + cc);
            const float v00 = acc[mt][nt][0] + bv.x, v01 = acc[mt][nt][1] + bv.y;
            const float v10 = acc[mt][nt][2] + bv.x, v11 = acc[mt][nt][3] + bv.y;
            OutT* p0 = C + (size_t)(row0 + r) * N + col0 + cc;
            OutT* p1 = C + (size_t)(row0 + r + 8) * N + col0 + cc;
            if constexpr (sizeof(OutT) == 4) {
                float2 o0, o1;
                o0.x = v00; o0.y = v01; o1.x = v10; o1.y = v11;
                *reinterpret_cast<float2*>(p0) = o0;
                *reinterpret_cast<float2*>(p1) = o1;
            } else {
                __half2 o0, o1;
                o0.x = __float2half(v00); o0.y = __float2half(v01);
                o1.x = __float2half(v10); o1.y = __float2half(v11);
                *reinterpret_cast<__half2*>(p0) = o0;
                *reinterpret_cast<__half2*>(p1) = o1;
            }
        }
    }
}

// ---------------------------------------------------------------------------
// fp32 -> fp16 convert
// ---------------------------------------------------------------------------
__global__ void __launch_bounds__(256)
convert_fp16(const float* __restrict__ src, __half* __restrict__ dst, long long n4)
{
    const long long i = (long long)blockIdx.x * blockDim.x + threadIdx.x;
    if (i >= n4) return;
    const float4 v = reinterpret_cast<const float4*>(src)[i];
    __half2 p0, p1;
    p0.x = __float2half(v.x); p0.y = __float2half(v.y);
    p1.x = __float2half(v.z); p1.y = __float2half(v.w);
    reinterpret_cast<__half2*>(dst)[2 * i]     = p0;
    reinterpret_cast<__half2*>(dst)[2 * i + 1] = p1;
}

// ---------------------------------------------------------------------------
// Causal depthwise conv (K=4) + bias + SiLU, fp16 in -> fp16 out
// SCH=64 (4096 blocks) to bound the serial per-thread chain.
// ---------------------------------------------------------------------------
#define SCH 64
__global__ void __launch_bounds__(256)
conv_silu(const __half* __restrict__ x, const float* __restrict__ cw,
          const float* __restrict__ cb, __half* __restrict__ y)
{
    const int c  = blockIdx.x * 256 + threadIdx.x;   // channel
    const int b  = blockIdx.z;
    const int s0 = blockIdx.y * SCH;

    const float4 w4 = *reinterpret_cast<const float4*>(cw + (size_t)c * 4);
    const float bias = cb[c];
    const size_t base = ((size_t)b * SEQ) * CH + c;

    float xm3, xm2, xm1;
    if (s0 == 0) { xm3 = xm2 = xm1 = 0.0f; }
    else {
        xm3 = __half2float(x[base + (size_t)(s0 - 3) * CH]);
        xm2 = __half2float(x[base + (size_t)(s0 - 2) * CH]);
        xm1 = __half2float(x[base + (size_t)(s0 - 1) * CH]);
    }

    for (int s = s0; s < s0 + SCH; s++) {
        const float xc = __half2float(x[base + (size_t)s * CH]);
        float acc = bias;
        acc = fmaf(w4.x, xm3, acc);
        acc = fmaf(w4.y, xm2, acc);
        acc = fmaf(w4.z, xm1, acc);
        acc = fmaf(w4.w, xc,  acc);
        const float v = acc / (1.0f + __expf(-acc));
        y[base + (size_t)s * CH] = __float2half(v);
        xm3 = xm2; xm2 = xm1; xm1 = xc;
    }
}

// ---------------------------------------------------------------------------
// Launch: hidden_states, w_in, b_in, conv_w, conv_b, w_out, b_out
// ---------------------------------------------------------------------------
extern "C" void kernel_launch(void* const* d_in, const int* in_sizes, int n_in,
                              void* d_out, int out_size)
{
    const float* hs     = (const float*)d_in[0];
    const float* w_in   = (const float*)d_in[1];
    const float* b_in   = (const float*)d_in[2];
    const float* conv_w = (const float*)d_in[3];
    const float* conv_b = (const float*)d_in[4];
    const float* w_out  = (const float*)d_in[5];
    const float* b_out  = (const float*)d_in[6];
    float* out = (float*)d_out;

    __half *hs16, *win16, *wout16, *xbuf, *ybuf;
    cudaGetSymbolAddress((void**)&hs16,   g_hs16);
    cudaGetSymbolAddress((void**)&win16,  g_win16);
    cudaGetSymbolAddress((void**)&wout16, g_wout16);
    cudaGetSymbolAddress((void**)&xbuf,   g_x);
    cudaGetSymbolAddress((void**)&ybuf,   g_y);

    cudaFuncSetAttribute(gemm_fp16<__half>, cudaFuncAttributeMaxDynamicSharedMemorySize, GEMM_SMEM);
    cudaFuncSetAttribute(gemm_fp16<float>,  cudaFuncAttributeMaxDynamicSharedMemorySize, GEMM_SMEM);

    // fp16 conversions
    {
        long long n4 = (long long)MROWS * HID / 4;
        convert_fp16<<<(unsigned)(n4 / 256), 256>>>(hs, hs16, n4);
        n4 = (long long)CH * HID / 4;
        convert_fp16<<<(unsigned)(n4 / 256), 256>>>(w_in, win16, n4);
        n4 = (long long)HID * CH / 4;
        convert_fp16<<<(unsigned)(n4 / 256), 256>>>(w_out, wout16, n4);
    }

    // GEMM1: x = hs @ w_in^T + b_in   [16384, 4096]  (fp16 out)
    {
        dim3 grid(CH / 128, MROWS / 128);   // (32, 128)
        gemm_fp16<__half><<<grid, 256, GEMM_SMEM>>>(hs16, win16, b_in, xbuf,
                                                    MROWS, CH, HID);
    }

    // conv + SiLU -> y (fp16)
    {
        dim3 grid(CH / 256, SEQ / SCH, BATCH);  // (16, 64, 4)
        conv_silu<<<grid, 256>>>(xbuf, conv_w, conv_b, ybuf);
    }

    // GEMM2: out = y @ w_out^T + b_out  [16384, 2048]  (fp32 out)
    {
        dim3 grid(HID / 128, MROWS / 128);  // (16, 128)
        gemm_fp16<float><<<grid, 256, GEMM_SMEM>>>(ybuf, wout16, b_out, out,
                                                   MROWS, HID, CH);
    }
}